// round 6
// baseline (speedup 1.0000x reference)
#include <cuda_runtime.h>

#define N_NODES 16384
#define A_ANCH  256
#define D_LAT   32

// Duplicated precomputed operands:
//   g_M_dup[a][d] = {m, m},  m = (1/A) * (anchor_emb @ W1)[a][d]
//   g_c_dup[d]    = {c, c},  c = b[d] + (1/A)*colsum(embeds[:A]) @ W2
__device__ float2 g_M_dup[A_ANCH * D_LAT];   // 64 KB
__device__ float2 g_c_dup[D_LAT];

// ---------------------------------------------------------------------------
// Kernel 1: precompute. Grid = 9 blocks x 256 threads.
// ---------------------------------------------------------------------------
__global__ __launch_bounds__(256) void precompute_kernel(
    const float* __restrict__ embeds,
    const float* __restrict__ W,       // [64,32]: W1 rows 0..31, W2 rows 32..63
    const float* __restrict__ b,       // [32]
    const int*   __restrict__ anchor_ids)
{
    __shared__ float Wsh[D_LAT * D_LAT];
    __shared__ float esh[32][32];
    __shared__ float ssh[D_LAT];

    const int t   = threadIdx.x;
    const int blk = blockIdx.x;
    const int j   = t & 31;

    if (blk < 8) {
        #pragma unroll
        for (int i = t; i < D_LAT * D_LAT; i += 256) Wsh[i] = W[i];
        for (int r = t >> 5; r < 32; r += 8) {
            int id = anchor_ids[blk * 32 + r];
            esh[r][j] = embeds[id * D_LAT + j];
        }
        __syncthreads();
        for (int r = t >> 5; r < 32; r += 8) {
            float acc = 0.f;
            #pragma unroll
            for (int d = 0; d < D_LAT; d++) acc += esh[r][d] * Wsh[d * D_LAT + j];
            float m = acc * (1.0f / 256.0f);
            g_M_dup[(blk * 32 + r) * D_LAT + j] = make_float2(m, m);
        }
    } else {
        #pragma unroll
        for (int i = t; i < D_LAT * D_LAT; i += 256) Wsh[i] = W[D_LAT * D_LAT + i];
        if (t < D_LAT) ssh[t] = 0.f;
        __syncthreads();
        {
            int grp = t >> 5;
            float part = 0.f;
            #pragma unroll 4
            for (int i = 0; i < 32; i++)
                part += embeds[(grp * 32 + i) * D_LAT + j];
            atomicAdd(&ssh[j], part);
        }
        __syncthreads();
        if (t < D_LAT) {
            float acc = 0.f;
            #pragma unroll
            for (int d = 0; d < D_LAT; d++) acc += ssh[d] * Wsh[d * D_LAT + t];
            float c = b[t] + acc * (1.0f / 256.0f);
            g_c_dup[t] = make_float2(c, c);
        }
    }
}

// ---------------------------------------------------------------------------
// Kernel 2: out[n,:] = sum_a dists[a,n] * M[a,:] + c   (n-packed f32x2)
//
// Block = 256 thr = 8 slots (4n) x 4 quarters (8d) x 8 a-groups (32a).
// Thread tile: 2 n-pairs x 8 d = 16 packed accs (~80 regs).
// 64 KB dyn smem (dup M; reused for single-round reduction). 3 blocks/SM.
// Grid 512 x 32n. PDL overlaps with kernel 1.
// ---------------------------------------------------------------------------
__global__ __launch_bounds__(256, 3) void pnn_main_kernel(
    const float* __restrict__ dists,   // [A, N]
    float*       __restrict__ out)     // [N, D]
{
    extern __shared__ __align__(16) unsigned long long sh[];  // 8192 u64 = 64 KB

    const int t       = threadIdx.x;
    const int slot    = t & 7;
    const int quarter = (t >> 3) & 3;
    const int group   = t >> 5;
    const int lane32  = t & 31;              // = slot + 8*quarter
    const int n0      = blockIdx.x * 32 + slot * 4;
    const int a0      = group * 32;

    // ---- dists prefetches first (independent of precompute kernel) ----
    const float* dp = dists + (size_t)a0 * N_NODES + n0;
    float4 pf[4];
    #pragma unroll
    for (int i = 0; i < 4; i++)
        pf[i] = *(const float4*)(dp + (size_t)i * N_NODES);

    // ---- wait for precompute results (PDL) ----
    cudaGridDependencySynchronize();

    // ---- copy duplicated M (64 KB) into shared ----
    {
        const float4* src = (const float4*)g_M_dup;
        float4*       dst = (float4*)sh;
        #pragma unroll
        for (int i = 0; i < 16; i++) dst[t + 256 * i] = src[t + 256 * i];
    }
    __syncthreads();

    unsigned long long acc[16];     // [pair p 0..1][d j 0..7]
    #pragma unroll
    for (int i = 0; i < 16; i++) acc[i] = 0ULL;

    const unsigned long long* mrow = sh + (size_t)a0 * D_LAT + quarter * 8;

    #pragma unroll
    for (int it = 0; it < 32; it += 4) {
        #pragma unroll
        for (int u = 0; u < 4; u++) {
            const int step = it + u;
            float4 d4 = pf[u];
            if (step + 4 < 32)
                pf[u] = *(const float4*)(dp + (size_t)(step + 4) * N_NODES);

            // two ready-made n-pairs, no packing movs
            unsigned long long dd0 = ((const ulonglong2*)&d4)->x;
            unsigned long long dd1 = ((const ulonglong2*)&d4)->y;

            const ulonglong2* mp = (const ulonglong2*)(mrow + (size_t)step * D_LAT);
            ulonglong2 m0 = mp[0], m1 = mp[1], m2 = mp[2], m3 = mp[3];

            #define FMA8(p, dd)                                                              \
                asm("fma.rn.f32x2 %0,%1,%2,%0;" : "+l"(acc[(p)*8+0]) : "l"(dd), "l"(m0.x)); \
                asm("fma.rn.f32x2 %0,%1,%2,%0;" : "+l"(acc[(p)*8+1]) : "l"(dd), "l"(m0.y)); \
                asm("fma.rn.f32x2 %0,%1,%2,%0;" : "+l"(acc[(p)*8+2]) : "l"(dd), "l"(m1.x)); \
                asm("fma.rn.f32x2 %0,%1,%2,%0;" : "+l"(acc[(p)*8+3]) : "l"(dd), "l"(m1.y)); \
                asm("fma.rn.f32x2 %0,%1,%2,%0;" : "+l"(acc[(p)*8+4]) : "l"(dd), "l"(m2.x)); \
                asm("fma.rn.f32x2 %0,%1,%2,%0;" : "+l"(acc[(p)*8+5]) : "l"(dd), "l"(m2.y)); \
                asm("fma.rn.f32x2 %0,%1,%2,%0;" : "+l"(acc[(p)*8+6]) : "l"(dd), "l"(m3.x)); \
                asm("fma.rn.f32x2 %0,%1,%2,%0;" : "+l"(acc[(p)*8+7]) : "l"(dd), "l"(m3.y));
            FMA8(0, dd0)
            FMA8(1, dd1)
            #undef FMA8
        }
    }

    // ---- single-round reduction over the 8 a-groups ----
    // store partials: sh[g*528 + k*33 + lane32], k = p*8 + j
    __syncthreads();   // M reads done; sh reusable
    #pragma unroll
    for (int k = 0; k < 16; k++)
        sh[group * 528 + k * 33 + lane32] = acc[k];
    __syncthreads();

    // each thread produces 2 final u64 outputs (o = t and o = t + 256)
    const unsigned long long* c64 = (const unsigned long long*)g_c_dup;
    const int bn0 = blockIdx.x * 32;

    #pragma unroll
    for (int h = 0; h < 2; h++) {
        const int o  = t + h * 256;          // 0..511
        const int P  = o >> 5;               // n-pair index 0..15
        const int d  = o & 31;               // column
        const int p  = P & 1;
        const int s  = P >> 1;
        const int j  = d & 7;
        const int q  = d >> 3;
        const int kk = p * 8 + j;
        const int ln = s + 8 * q;
        const int base = kk * 33 + ln;

        unsigned long long r = sh[base];
        #pragma unroll
        for (int g = 1; g < 8; g++)
            asm("add.rn.f32x2 %0,%0,%1;" : "+l"(r) : "l"(sh[g * 528 + base]));
        asm("add.rn.f32x2 %0,%0,%1;" : "+l"(r) : "l"(c64[d]));

        float lo, hi;
        asm("mov.b64 {%0,%1}, %2;" : "=f"(lo), "=f"(hi) : "l"(r));
        out[(size_t)(bn0 + 2 * P)     * D_LAT + d] = lo;
        out[(size_t)(bn0 + 2 * P + 1) * D_LAT + d] = hi;
    }
}

extern "C" void kernel_launch(void* const* d_in, const int* in_sizes, int n_in,
                              void* d_out, int out_size)
{
    const float* embeds     = (const float*)d_in[0];
    const float* dists      = (const float*)d_in[1];
    const float* W_hidden   = (const float*)d_in[2];
    const float* b_hidden   = (const float*)d_in[3];
    const int*   anchor_ids = (const int*)  d_in[4];
    float*       out        = (float*)d_out;

    cudaFuncSetAttribute(pnn_main_kernel,
                         cudaFuncAttributeMaxDynamicSharedMemorySize, 65536);

    precompute_kernel<<<9, 256>>>(embeds, W_hidden, b_hidden, anchor_ids);

    cudaLaunchConfig_t cfg = {};
    cfg.gridDim  = dim3(N_NODES / 32, 1, 1);
    cfg.blockDim = dim3(256, 1, 1);
    cfg.dynamicSmemBytes = 65536;
    cfg.stream = 0;
    cudaLaunchAttribute attr[1];
    attr[0].id = cudaLaunchAttributeProgrammaticStreamSerialization;
    attr[0].val.programmaticStreamSerializationAllowed = 1;
    cfg.attrs = attr;
    cfg.numAttrs = 1;

    cudaError_t e = cudaLaunchKernelEx(&cfg, pnn_main_kernel, dists, out);
    if (e != cudaSuccess) {
        pnn_main_kernel<<<N_NODES / 32, 256, 65536>>>(dists, out);
    }
}

// round 7
// speedup vs baseline: 1.1067x; 1.1067x over previous
#include <cuda_runtime.h>

#define N_NODES 16384
#define A_ANCH  256
#define D_LAT   32

// Duplicated precomputed operands:
//   g_M_dup[a][d] = {m, m},  m = (1/A) * (anchor_emb @ W1)[a][d]
//   g_c_dup[d]    = {c, c},  c = b[d] + (1/A)*colsum(embeds[:A]) @ W2
__device__ float2 g_M_dup[A_ANCH * D_LAT];   // 64 KB
__device__ float2 g_c_dup[D_LAT];

// ---------------------------------------------------------------------------
// Kernel 1: precompute. Grid = 9 blocks x 256 threads.
// ---------------------------------------------------------------------------
__global__ __launch_bounds__(256) void precompute_kernel(
    const float* __restrict__ embeds,
    const float* __restrict__ W,       // [64,32]: W1 rows 0..31, W2 rows 32..63
    const float* __restrict__ b,       // [32]
    const int*   __restrict__ anchor_ids)
{
    __shared__ float Wsh[D_LAT * D_LAT];
    __shared__ float esh[32][32];
    __shared__ float ssh[D_LAT];

    const int t   = threadIdx.x;
    const int blk = blockIdx.x;
    const int j   = t & 31;

    if (blk < 8) {
        #pragma unroll
        for (int i = t; i < D_LAT * D_LAT; i += 256) Wsh[i] = W[i];
        for (int r = t >> 5; r < 32; r += 8) {
            int id = anchor_ids[blk * 32 + r];
            esh[r][j] = embeds[id * D_LAT + j];
        }
        __syncthreads();
        for (int r = t >> 5; r < 32; r += 8) {
            float acc = 0.f;
            #pragma unroll
            for (int d = 0; d < D_LAT; d++) acc += esh[r][d] * Wsh[d * D_LAT + j];
            float m = acc * (1.0f / 256.0f);
            g_M_dup[(blk * 32 + r) * D_LAT + j] = make_float2(m, m);
        }
    } else {
        #pragma unroll
        for (int i = t; i < D_LAT * D_LAT; i += 256) Wsh[i] = W[D_LAT * D_LAT + i];
        if (t < D_LAT) ssh[t] = 0.f;
        __syncthreads();
        {
            int grp = t >> 5;
            float part = 0.f;
            #pragma unroll 4
            for (int i = 0; i < 32; i++)
                part += embeds[(grp * 32 + i) * D_LAT + j];
            atomicAdd(&ssh[j], part);
        }
        __syncthreads();
        if (t < D_LAT) {
            float acc = 0.f;
            #pragma unroll
            for (int d = 0; d < D_LAT; d++) acc += ssh[d] * Wsh[d * D_LAT + t];
            float c = b[t] + acc * (1.0f / 256.0f);
            g_c_dup[t] = make_float2(c, c);
        }
    }
}

// ---------------------------------------------------------------------------
// Kernel 2: out[n,:] = sum_a dists[a,n] * M[a,:] + c   (n-packed f32x2)
//
// Block = 256 thr = 8 slots (8n each) x 4 quarters (8d each) x 8 a-groups.
// Thread tile: 4 n-pairs x 8 d = 32 packed accs (64 regs), ~116 regs total.
// Per step: 2 LDG.128 + 4 LDS.128 + 32 FFMA2, zero packing movs.
// Smem 67584 B: dup M (64 KB) for main loop, padded partials for the
// single-round reduction afterwards. 2 blocks/SM, grid 256 = 1 wave.
// ---------------------------------------------------------------------------
#define SMEM_U64 8448   // 8 groups * 32 k * 33 pad = 8448 u64 = 67584 B

__global__ __launch_bounds__(256, 2) void pnn_main_kernel(
    const float* __restrict__ dists,   // [A, N]
    float*       __restrict__ out)     // [N, D]
{
    extern __shared__ __align__(16) unsigned long long sh[];

    const int t       = threadIdx.x;
    const int slot    = t & 7;
    const int quarter = (t >> 3) & 3;
    const int group   = t >> 5;
    const int lane32  = t & 31;
    const int n0      = blockIdx.x * 64 + slot * 8;
    const int a0      = group * 32;

    // ---- dists prefetches first (proceed during precompute via PDL) ----
    const float* dp = dists + (size_t)a0 * N_NODES + n0;
    float4 pfA[3], pfB[3];
    #pragma unroll
    for (int i = 0; i < 3; i++) {
        pfA[i] = *(const float4*)(dp + (size_t)i * N_NODES);
        pfB[i] = *(const float4*)(dp + (size_t)i * N_NODES + 4);
    }

    // ---- wait for precompute results ----
    cudaGridDependencySynchronize();

    // ---- copy duplicated M (64 KB) into shared ----
    {
        const float4* src = (const float4*)g_M_dup;
        float4*       dst = (float4*)sh;
        #pragma unroll
        for (int i = 0; i < 16; i++) dst[t + 256 * i] = src[t + 256 * i];
    }
    __syncthreads();

    unsigned long long acc[32];   // [pair p 0..3][d j 0..7]
    #pragma unroll
    for (int i = 0; i < 32; i++) acc[i] = 0ULL;

    const unsigned long long* mrow = sh + (size_t)a0 * D_LAT + quarter * 8;

    #pragma unroll
    for (int it = 0; it < 30; it += 3) {
        #pragma unroll
        for (int u = 0; u < 3; u++) {
            const int step = it + u;
            float4 dA = pfA[u];
            float4 dB = pfB[u];
            if (step + 3 < 32) {
                pfA[u] = *(const float4*)(dp + (size_t)(step + 3) * N_NODES);
                pfB[u] = *(const float4*)(dp + (size_t)(step + 3) * N_NODES + 4);
            }
            unsigned long long dd0 = ((const ulonglong2*)&dA)->x;
            unsigned long long dd1 = ((const ulonglong2*)&dA)->y;
            unsigned long long dd2 = ((const ulonglong2*)&dB)->x;
            unsigned long long dd3 = ((const ulonglong2*)&dB)->y;

            const ulonglong2* mp = (const ulonglong2*)(mrow + (size_t)step * D_LAT);
            ulonglong2 m0 = mp[0], m1 = mp[1], m2 = mp[2], m3 = mp[3];

            #define FMA8(p, dd)                                                              \
                asm("fma.rn.f32x2 %0,%1,%2,%0;" : "+l"(acc[(p)*8+0]) : "l"(dd), "l"(m0.x)); \
                asm("fma.rn.f32x2 %0,%1,%2,%0;" : "+l"(acc[(p)*8+1]) : "l"(dd), "l"(m0.y)); \
                asm("fma.rn.f32x2 %0,%1,%2,%0;" : "+l"(acc[(p)*8+2]) : "l"(dd), "l"(m1.x)); \
                asm("fma.rn.f32x2 %0,%1,%2,%0;" : "+l"(acc[(p)*8+3]) : "l"(dd), "l"(m1.y)); \
                asm("fma.rn.f32x2 %0,%1,%2,%0;" : "+l"(acc[(p)*8+4]) : "l"(dd), "l"(m2.x)); \
                asm("fma.rn.f32x2 %0,%1,%2,%0;" : "+l"(acc[(p)*8+5]) : "l"(dd), "l"(m2.y)); \
                asm("fma.rn.f32x2 %0,%1,%2,%0;" : "+l"(acc[(p)*8+6]) : "l"(dd), "l"(m3.x)); \
                asm("fma.rn.f32x2 %0,%1,%2,%0;" : "+l"(acc[(p)*8+7]) : "l"(dd), "l"(m3.y));
            FMA8(0, dd0)
            FMA8(1, dd1)
            FMA8(2, dd2)
            FMA8(3, dd3)
            #undef FMA8
        }
    }
    // ---- last 2 steps (30, 31), no further prefetch ----
    #pragma unroll
    for (int u = 0; u < 2; u++) {
        const int step = 30 + u;
        float4 dA = pfA[u];
        float4 dB = pfB[u];
        unsigned long long dd0 = ((const ulonglong2*)&dA)->x;
        unsigned long long dd1 = ((const ulonglong2*)&dA)->y;
        unsigned long long dd2 = ((const ulonglong2*)&dB)->x;
        unsigned long long dd3 = ((const ulonglong2*)&dB)->y;

        const ulonglong2* mp = (const ulonglong2*)(mrow + (size_t)step * D_LAT);
        ulonglong2 m0 = mp[0], m1 = mp[1], m2 = mp[2], m3 = mp[3];

        #define FMA8(p, dd)                                                              \
            asm("fma.rn.f32x2 %0,%1,%2,%0;" : "+l"(acc[(p)*8+0]) : "l"(dd), "l"(m0.x)); \
            asm("fma.rn.f32x2 %0,%1,%2,%0;" : "+l"(acc[(p)*8+1]) : "l"(dd), "l"(m0.y)); \
            asm("fma.rn.f32x2 %0,%1,%2,%0;" : "+l"(acc[(p)*8+2]) : "l"(dd), "l"(m1.x)); \
            asm("fma.rn.f32x2 %0,%1,%2,%0;" : "+l"(acc[(p)*8+3]) : "l"(dd), "l"(m1.y)); \
            asm("fma.rn.f32x2 %0,%1,%2,%0;" : "+l"(acc[(p)*8+4]) : "l"(dd), "l"(m2.x)); \
            asm("fma.rn.f32x2 %0,%1,%2,%0;" : "+l"(acc[(p)*8+5]) : "l"(dd), "l"(m2.y)); \
            asm("fma.rn.f32x2 %0,%1,%2,%0;" : "+l"(acc[(p)*8+6]) : "l"(dd), "l"(m3.x)); \
            asm("fma.rn.f32x2 %0,%1,%2,%0;" : "+l"(acc[(p)*8+7]) : "l"(dd), "l"(m3.y));
        FMA8(0, dd0)
        FMA8(1, dd1)
        FMA8(2, dd2)
        FMA8(3, dd3)
        #undef FMA8
    }

    // ---- single-round reduction over the 8 a-groups ----
    // partials: sh[(g*32 + k)*33 + lane32], k = p*8 + j  (stores conflict-free)
    __syncthreads();
    #pragma unroll
    for (int k = 0; k < 32; k++)
        sh[(group * 32 + k) * 33 + lane32] = acc[k];
    __syncthreads();

    // each thread produces 4 final u64 outputs (1024 per block)
    const unsigned long long* c64 = (const unsigned long long*)g_c_dup;
    const int bn0 = blockIdx.x * 64;

    #pragma unroll
    for (int h = 0; h < 4; h++) {
        const int o   = t + h * 256;        // 0..1023
        const int P   = o >> 5;             // n-pair 0..31
        const int d   = o & 31;             // column
        const int p   = P & 3;
        const int s   = P >> 2;
        const int j   = d & 7;
        const int q   = d >> 3;
        const int base = (p * 8 + j) * 33 + s + 8 * q;

        unsigned long long r = sh[base];
        #pragma unroll
        for (int g = 1; g < 8; g++)
            asm("add.rn.f32x2 %0,%0,%1;" : "+l"(r) : "l"(sh[g * 1056 + base]));
        asm("add.rn.f32x2 %0,%0,%1;" : "+l"(r) : "l"(c64[d]));

        float lo, hi;
        asm("mov.b64 {%0,%1}, %2;" : "=f"(lo), "=f"(hi) : "l"(r));
        out[(size_t)(bn0 + 2 * P)     * D_LAT + d] = lo;
        out[(size_t)(bn0 + 2 * P + 1) * D_LAT + d] = hi;
    }
}

extern "C" void kernel_launch(void* const* d_in, const int* in_sizes, int n_in,
                              void* d_out, int out_size)
{
    const float* embeds     = (const float*)d_in[0];
    const float* dists      = (const float*)d_in[1];
    const float* W_hidden   = (const float*)d_in[2];
    const float* b_hidden   = (const float*)d_in[3];
    const int*   anchor_ids = (const int*)  d_in[4];
    float*       out        = (float*)d_out;

    cudaFuncSetAttribute(pnn_main_kernel,
                         cudaFuncAttributeMaxDynamicSharedMemorySize,
                         SMEM_U64 * 8);

    precompute_kernel<<<9, 256>>>(embeds, W_hidden, b_hidden, anchor_ids);

    cudaLaunchConfig_t cfg = {};
    cfg.gridDim  = dim3(N_NODES / 64, 1, 1);
    cfg.blockDim = dim3(256, 1, 1);
    cfg.dynamicSmemBytes = SMEM_U64 * 8;
    cfg.stream = 0;
    cudaLaunchAttribute attr[1];
    attr[0].id = cudaLaunchAttributeProgrammaticStreamSerialization;
    attr[0].val.programmaticStreamSerializationAllowed = 1;
    cfg.attrs = attr;
    cfg.numAttrs = 1;

    cudaError_t e = cudaLaunchKernelEx(&cfg, pnn_main_kernel, dists, out);
    if (e != cudaSuccess) {
        pnn_main_kernel<<<N_NODES / 64, 256, SMEM_U64 * 8>>>(dists, out);
    }
}